// round 3
// baseline (speedup 1.0000x reference)
#include <cuda_runtime.h>
#include <math.h>
#include <stdint.h>

#define DK 256
#define DEMB 768
#define CH 32
#define TMAX 1000
#define PMAX 200
#define NCHS_MAX 32
#define NCHP_MAX 7

#define S_DECAY 0.95f
#define P_DECAY 0.99f
#define ALPHA   0.1f
#define BETA    1.0f
#define EPSN    1e-12f

// ---------------- device scratch ----------------
__device__ float g_K [TMAX*DK];    // raw K
__device__ float g_Kn[TMAX*DK];    // normalized K
__device__ float g_V [TMAX*DK];
__device__ float g_PK[PMAX*DK];    // normalized PK
__device__ float g_PV[PMAX*DK];    // raw PV
__device__ float g_T [(NCHS_MAX + 2*NCHP_MAX)*CH*CH]; // [slot][j][k], scan-order
__device__ float g_c [NCHP_MAX*CH];  // fwd constant vector
__device__ float g_res[4*DK];
__device__ int   g_done;

// ---------------- small helpers ----------------
__device__ __forceinline__ unsigned long long pack2(float lo, float hi) {
    unsigned long long r;
    asm("mov.b64 %0, {%1, %2};" : "=l"(r) : "f"(lo), "f"(hi));
    return r;
}
__device__ __forceinline__ unsigned long long fma2(unsigned long long a,
                                                   unsigned long long b,
                                                   unsigned long long c) {
    unsigned long long d;
    asm("fma.rn.f32x2 %0, %1, %2, %3;" : "=l"(d) : "l"(a), "l"(b), "l"(c));
    return d;
}
__device__ __forceinline__ void unpack2(unsigned long long v, float& lo, float& hi) {
    asm("mov.b64 {%0, %1}, %2;" : "=f"(lo), "=f"(hi) : "l"(v));
}
__device__ __forceinline__ uint32_t smem_u32(const void* p) {
    uint32_t a;
    asm("{ .reg .u64 t; cvta.to.shared.u64 t, %1; cvt.u32.u64 %0, t; }" : "=r"(a) : "l"(p));
    return a;
}
__device__ __forceinline__ void mbar_init(uint32_t a, uint32_t n) {
    asm volatile("mbarrier.init.shared.b64 [%0], %1;" :: "r"(a), "r"(n) : "memory");
}
__device__ __forceinline__ void mbar_expect(uint32_t a, uint32_t bytes) {
    asm volatile("mbarrier.arrive.expect_tx.shared.b64 _, [%0], %1;" :: "r"(a), "r"(bytes) : "memory");
}
__device__ __forceinline__ void bulk_g2s(uint32_t dst, const void* src, uint32_t bytes, uint32_t mbar) {
    asm volatile("cp.async.bulk.shared::cluster.global.mbarrier::complete_tx::bytes [%0], [%1], %2, [%3];"
                 :: "r"(dst), "l"(src), "r"(bytes), "r"(mbar) : "memory");
}
__device__ __forceinline__ void mbar_wait(uint32_t a, uint32_t parity) {
    asm volatile(
        "{\n\t.reg .pred P;\n"
        "W_%=:\n\t"
        "mbarrier.try_wait.parity.acquire.cta.shared::cta.b64 P, [%0], %1, 0x989680;\n\t"
        "@P bra.uni D_%=;\n\t"
        "bra.uni W_%=;\n"
        "D_%=:\n\t}"
        :: "r"(a), "r"(parity) : "memory");
}

// ---------------- kernel 1: K = emb@Wk + bk ; V = emb@Wv + bv (f32x2) ----------------
__global__ void __launch_bounds__(256) k_kv(const float* __restrict__ emb,
                     const float* __restrict__ Wk, const float* __restrict__ bk,
                     const float* __restrict__ Wv, const float* __restrict__ bv,
                     int T)
{
    // transposed emb tile: est[e*12 + r], stride 12 keeps every e 16B-aligned
    __shared__ __align__(16) float est[DEMB*12];
    const int tid = threadIdx.x;
    const int r0  = blockIdx.x * 8;
    const int rows = min(8, T - r0);

    for (int idx = tid; idx < 8*DEMB; idx += 256) {
        int r = idx / DEMB, e = idx - r*DEMB;
        est[e*12 + r] = (r < rows) ? emb[(r0 + r)*DEMB + e] : 0.f;
    }
    __syncthreads();

    unsigned long long aK[4], aV[4];
    #pragma unroll
    for (int p = 0; p < 4; p++) { aK[p] = pack2(0.f, 0.f); aV[p] = pack2(0.f, 0.f); }

    #pragma unroll 4
    for (int e = 0; e < DEMB; e++) {
        float wk = Wk[e*DK + tid];
        float wv = Wv[e*DK + tid];
        unsigned long long wk2 = pack2(wk, wk);
        unsigned long long wv2 = pack2(wv, wv);
        ulonglong2 p01 = *(const ulonglong2*)&est[e*12];
        ulonglong2 p23 = *(const ulonglong2*)&est[e*12 + 4];
        aK[0] = fma2(p01.x, wk2, aK[0]);  aV[0] = fma2(p01.x, wv2, aV[0]);
        aK[1] = fma2(p01.y, wk2, aK[1]);  aV[1] = fma2(p01.y, wv2, aV[1]);
        aK[2] = fma2(p23.x, wk2, aK[2]);  aV[2] = fma2(p23.x, wv2, aV[2]);
        aK[3] = fma2(p23.y, wk2, aK[3]);  aV[3] = fma2(p23.y, wv2, aV[3]);
    }

    float bkv = bk[tid], bvv = bv[tid];
    #pragma unroll
    for (int p = 0; p < 4; p++) {
        float k0,k1,v0,v1;
        unpack2(aK[p], k0, k1);
        unpack2(aV[p], v0, v1);
        int r = 2*p;
        if (r < rows)     { g_K[(r0+r  )*DK + tid] = k0 + bkv; g_V[(r0+r  )*DK + tid] = v0 + bvv; }
        if (r + 1 < rows) { g_K[(r0+r+1)*DK + tid] = k1 + bkv; g_V[(r0+r+1)*DK + tid] = v1 + bvv; }
    }
}

// ---------------- kernel 2: fused para-means + normalize + Gram + inverses ----------------
// blocks [0, nchS): sentence chunks (bwd inverse).
// blocks [nchS, nchS+nchP): paragraph chunks (means, Pm, bwd+fwd inverses, fwd constants).
__global__ void __launch_bounds__(256) k_prep(int T, int P, int nchS, int nchP)
{
    extern __shared__ __align__(16) float dyn[];
    float* ks = dyn;            // 32*260
    float* vs = dyn + 8320;     // 32*260 (para only)
    __shared__ float Gs [CH*33];
    __shared__ float Tsb[CH*33];
    __shared__ float Tsf[CH*33];
    __shared__ float Pm[CH];
    __shared__ float fsv[CH], lfs[CH];

    const int cid = blockIdx.x, tid = threadIdx.x;
    const int wid = tid >> 5, lane = tid & 31;

    if (cid == 0 && tid == 0) g_done = 0;

    const bool isPara = (cid >= nchS);
    const int chunk = isPara ? (cid - nchS) : cid;
    const int steps = isPara ? P : T;
    const int lo  = chunk * CH;
    const int len = min(CH, steps - lo);

    if (!isPara) {
        // load raw K chunk (float4), zero-pad
        #pragma unroll
        for (int u = 0; u < 8; u++) {
            int id = tid + 256*u;
            int a = id >> 6, c4 = (id & 63) * 4;
            float4 v = make_float4(0.f,0.f,0.f,0.f);
            if (a < len) v = *(const float4*)&g_K[(lo + a)*DK + c4];
            *(float4*)&ks[a*260 + c4] = v;
        }
    } else {
        // PK/PV = 5-group means of raw K/V
        #pragma unroll
        for (int g = 0; g < 8; g++) {
            int r  = (tid >> 6) + 4*g;
            int c4 = (tid & 63) * 4;
            float4 ak = make_float4(0.f,0.f,0.f,0.f);
            float4 av = make_float4(0.f,0.f,0.f,0.f);
            if (r < len) {
                #pragma unroll
                for (int i = 0; i < 5; i++) {
                    float4 kk = *(const float4*)&g_K[((lo + r)*5 + i)*DK + c4];
                    float4 vv = *(const float4*)&g_V[((lo + r)*5 + i)*DK + c4];
                    ak.x += kk.x; ak.y += kk.y; ak.z += kk.z; ak.w += kk.w;
                    av.x += vv.x; av.y += vv.y; av.z += vv.z; av.w += vv.w;
                }
                ak.x *= 0.2f; ak.y *= 0.2f; ak.z *= 0.2f; ak.w *= 0.2f;
                av.x *= 0.2f; av.y *= 0.2f; av.z *= 0.2f; av.w *= 0.2f;
                *(float4*)&g_PV[(lo + r)*DK + c4] = av;
            }
            *(float4*)&ks[r*260 + c4] = ak;
            *(float4*)&vs[r*260 + c4] = av;
        }
    }
    __syncthreads();

    if (isPara) {
        // Pm[r] = mean over dv of PV row r (local chunk indexing)
        #pragma unroll
        for (int rr = 0; rr < 4; rr++) {
            int r = wid*4 + rr;
            float s = 0.f;
            #pragma unroll
            for (int m = 0; m < 8; m++) s += vs[r*260 + lane + 32*m];
            #pragma unroll
            for (int o = 16; o; o >>= 1) s += __shfl_xor_sync(0xffffffffu, s, o);
            if (lane == 0) Pm[r] = s * (1.f/256.f);
        }
    }

    // normalize rows of ks in smem; write g_Kn / g_PK
    {
        float* gout = isPara ? g_PK : g_Kn;
        #pragma unroll
        for (int rr = 0; rr < 4; rr++) {
            int r = wid*4 + rr;
            float v[8]; float s = 0.f;
            #pragma unroll
            for (int m = 0; m < 8; m++) { v[m] = ks[r*260 + lane + 32*m]; s += v[m]*v[m]; }
            #pragma unroll
            for (int o = 16; o; o >>= 1) s += __shfl_xor_sync(0xffffffffu, s, o);
            float rinv = 1.f / fmaxf(sqrtf(s), EPSN);
            #pragma unroll
            for (int m = 0; m < 8; m++) {
                float nv = v[m] * rinv;
                ks[r*260 + lane + 32*m] = nv;
                if (r < len) gout[(lo + r)*DK + lane + 32*m] = nv;
            }
        }
    }
    __syncthreads();

    // Gram on normalized chunk
    {
        float acc[4] = {0.f,0.f,0.f,0.f};
        #pragma unroll 8
        for (int i4 = 0; i4 < 64; i4++) {
            float4 own = *(const float4*)&ks[lane*260 + i4*4];
            #pragma unroll
            for (int s = 0; s < 4; s++) {
                float4 b = *(const float4*)&ks[(wid + 8*s)*260 + i4*4];
                acc[s] += own.x*b.x + own.y*b.y + own.z*b.z + own.w*b.w;
            }
        }
        #pragma unroll
        for (int s = 0; s < 4; s++) Gs[(wid + 8*s)*33 + lane] = acc[s];
    }
    __syncthreads();

    // triangular inverses of (I + alpha*L) in scan order
    if (!isPara) {
        #pragma unroll
        for (int cc = 0; cc < 4; cc++) {
            int k = wid*4 + cc;
            float v = (lane == k) ? 1.f : 0.f;
            for (int i = 0; i < len; i++) {
                float vi = __shfl_sync(0xffffffffu, v, i);
                if (lane > i && lane < len)
                    v -= ALPHA * Gs[(len-1-lane)*33 + (len-1-i)] * vi;
            }
            Tsb[lane*33 + k] = v;
        }
    } else {
        const bool fw = (wid >= 4);
        #pragma unroll
        for (int cc = 0; cc < 8; cc++) {
            int k = (wid & 3)*8 + cc;
            float v = (lane == k) ? 1.f : 0.f;
            for (int i = 0; i < len; i++) {
                float vi = __shfl_sync(0xffffffffu, v, i);
                if (lane > i && lane < len) {
                    float gg = fw ? Gs[lane*33 + i]
                                  : Gs[(len-1-lane)*33 + (len-1-i)];
                    v -= ALPHA * gg * vi;
                }
            }
            (fw ? Tsf : Tsb)[lane*33 + k] = v;
        }
    }
    __syncthreads();

    // fwd constants: c = -alpha * T_f (L f) + f, f_j = beta d^-(j+1) Pm_j
    if (isPara && wid == 0) {
        float f = 0.f;
        if (lane < len) {
            float dp = 1.f;
            for (int i = 0; i <= lane; i++) dp *= (1.f / P_DECAY);
            f = BETA * dp * Pm[lane];
        }
        fsv[lane] = f;
        __syncwarp();
        float lf = 0.f;
        if (lane < len)
            for (int i = 0; i < lane; i++) lf += Gs[lane*33 + i] * fsv[i];
        lfs[lane] = lf;
        __syncwarp();
        float e = 0.f;
        #pragma unroll 8
        for (int k2 = 0; k2 < CH; k2++) e += Tsf[lane*33 + k2] * lfs[k2];
        g_c[chunk*CH + lane] = -ALPHA * e + f;
    }

    // store T matrices coalesced
    {
        int slotb = isPara ? (nchS + chunk) : chunk;
        #pragma unroll
        for (int it = 0; it < 4; it++) {
            int idx = tid + 256*it;
            g_T[slotb*1024 + idx] = Tsb[(idx >> 5)*33 + (idx & 31)];
        }
        if (isPara) {
            int slotf = nchS + nchP + chunk;
            #pragma unroll
            for (int it = 0; it < 4; it++) {
                int idx = tid + 256*it;
                g_T[slotf*1024 + idx] = Tsf[(idx >> 5)*33 + (idx & 31)];
            }
        }
    }
}

// ---------------- kernel 3: TMA-pipelined chunked scans + final combine ----------------
// bid 0: sentence bwd, probe qn              (combines final output)
// bid 1: para bwd, probes {qn, 1/dk}         -> g_res[1], g_res[2]
// bid 2: para fwd, v-mean weights            -> g_res[3] (doc_k)
#define BUFS 3
#define BUF_FLOATS 17440   // K 8192 + V 8192 + T 1024 + c 32
__device__ __forceinline__ float bred256(float x, float* red) {
    const int tid = threadIdx.x;
    #pragma unroll
    for (int o = 16; o; o >>= 1) x += __shfl_xor_sync(0xffffffffu, x, o);
    __syncthreads();
    if ((tid & 31) == 0) red[tid >> 5] = x;
    __syncthreads();
    float s = 0.f;
    #pragma unroll
    for (int w = 0; w < 8; w++) s += red[w];
    return s;
}

__global__ void __launch_bounds__(256) k_scan(const float* __restrict__ q,
                                              float* __restrict__ out,
                                              int T, int P, int nchS, int nchP)
{
    extern __shared__ __align__(16) float dyn[];
    __shared__ float a1_s[DK], a2_s[DK];
    __shared__ float b1_s[CH], b2_s[CH];
    __shared__ float sk1_s[CH], sv1_s[CH], sk2_s[CH], sv2_s[CH];
    __shared__ float dpow[CH+1];
    __shared__ float red[8];
    __shared__ float s_inv;
    __shared__ __align__(8) unsigned long long mb[BUFS];

    const int bid = blockIdx.x, tid = threadIdx.x;
    const int wid = tid >> 5, lane = tid & 31;
    const bool sent = (bid == 0);
    const bool fwd  = (bid == 2);
    const bool dual = (bid == 1);
    const bool hasV = !fwd;
    const float decay = sent ? S_DECAY : P_DECAY;
    const int nch   = sent ? nchS : nchP;
    const int steps = sent ? T : P;
    const float* Ksrc = sent ? g_Kn : g_PK;
    const float* Vsrc = sent ? g_V  : g_PV;
    const int slot0 = sent ? 0 : (fwd ? (nchS + nchP) : nchS);
    const uint32_t dynb = smem_u32(dyn);

    if (tid == 0) {
        #pragma unroll
        for (int i = 0; i < BUFS; i++) mbar_init(smem_u32(&mb[i]), 1);
        dpow[0] = 1.f;
        for (int i = 0; i < CH; i++) dpow[i+1] = dpow[i] * decay;
    }

    // q normalization (all blocks compute; used by 0,1 and block 0's epilogue)
    float qv = q[tid];
    {
        float x = qv * qv;
        #pragma unroll
        for (int o = 16; o; o >>= 1) x += __shfl_xor_sync(0xffffffffu, x, o);
        if (lane == 0) red[wid] = x;
        __syncthreads();
        if (tid == 0) {
            float s = 0.f;
            #pragma unroll
            for (int w = 0; w < 8; w++) s += red[w];
            s_inv = 1.f / fmaxf(sqrtf(s), EPSN);
        }
        __syncthreads();
    }
    float a1 = 0.f, a2 = 0.f;
    if (bid == 0)      { a1 = qv * s_inv; }
    else if (bid == 1) { a1 = qv * s_inv; a2 = 1.f/256.f; }
    a1_s[tid] = a1; a2_s[tid] = a2;
    __syncthreads();   // mbar init + a_s visible

    // TMA issue helper
    auto issue = [&](int c_iter) {
        int ch  = fwd ? c_iter : (nch - 1 - c_iter);
        int buf = c_iter % BUFS;
        int ln  = min(CH, steps - ch*CH);
        uint32_t kb  = (uint32_t)ln * 1024u;
        uint32_t mba = smem_u32(&mb[buf]);
        uint32_t dst = dynb + (uint32_t)buf * (BUF_FLOATS*4u);
        uint32_t tot = kb + 4096u + (hasV ? kb : 0u) + (fwd ? 128u : 0u);
        mbar_expect(mba, tot);
        bulk_g2s(dst,          Ksrc + ch*CH*DK, kb, mba);
        if (hasV) bulk_g2s(dst + 32768u, Vsrc + ch*CH*DK, kb, mba);
        bulk_g2s(dst + 65536u, g_T + (slot0 + ch)*CH*CH, 4096u, mba);
        if (fwd)  bulk_g2s(dst + 69632u, g_c + ch*CH, 128u, mba);
    };
    if (tid == 0) {
        issue(0);
        if (nch > 1) issue(1);
    }

    float out1 = 0.f, out2 = 0.f;
    const int j0 = wid * 4;

    for (int c = 0; c < nch; c++) {
        const int chunk = fwd ? c : (nch - 1 - c);
        const int len = min(CH, steps - chunk*CH);
        __syncthreads();                         // prev stage B done; a_s ready
        if (tid == 0 && c + 2 < nch) issue(c + 2);
        mbar_wait(smem_u32(&mb[c % BUFS]), (c / BUFS) & 1);

        float* Kb = dyn + (c % BUFS)*BUF_FLOATS;
        float* Vb = Kb + 8192;
        float* Tb = Kb + 16384;
        float* cb = Kb + 17408;

        // zero scratch: sig slots + stale rows beyond len
        if (tid < CH) { sk1_s[tid] = 0.f; sv1_s[tid] = 0.f; sk2_s[tid] = 0.f; sv2_s[tid] = 0.f; }
        if (len < CH) {
            for (int i = tid; i < (CH - len)*DK; i += 256) {
                Kb[len*DK + i] = 0.f;
                if (hasV) Vb[len*DK + i] = 0.f;
            }
        }

        // stage A: b_j = kn_(scan j) . a
        float av1[8], av2[8];
        #pragma unroll
        for (int m = 0; m < 8; m++) {
            av1[m] = a1_s[lane + 32*m];
            av2[m] = dual ? a2_s[lane + 32*m] : 0.f;
        }
        float s1[4], s2[4];
        #pragma unroll
        for (int r = 0; r < 4; r++) {
            int j = j0 + r;
            int slot = (j < len) ? (fwd ? j : (len - 1 - j)) : 0;
            const float* kr = Kb + slot*DK;
            float t1 = 0.f, t2 = 0.f;
            #pragma unroll
            for (int m = 0; m < 8; m++) {
                float kk = kr[lane + 32*m];
                t1 += kk * av1[m];
                t2 += kk * av2[m];
            }
            s1[r] = t1; s2[r] = t2;
        }
        #pragma unroll
        for (int o = 16; o; o >>= 1) {
            #pragma unroll
            for (int r = 0; r < 4; r++) {
                s1[r] += __shfl_xor_sync(0xffffffffu, s1[r], o);
                s2[r] += __shfl_xor_sync(0xffffffffu, s2[r], o);
            }
        }
        if (lane == 0) {
            #pragma unroll
            for (int r = 0; r < 4; r++) {
                int j = j0 + r;
                b1_s[j] = (j < len) ? s1[r] : 0.f;
                b2_s[j] = (j < len) ? s2[r] : 0.f;
            }
        }
        __syncthreads();

        // stage A2: sig = T b (+ c for fwd); write weights by SLOT index
        #pragma unroll
        for (int r = 0; r < 4; r++) {
            int j = j0 + r;
            float tj = Tb[j*CH + lane];
            float x1 = tj * b1_s[lane];
            float x2 = dual ? tj * b2_s[lane] : 0.f;
            #pragma unroll
            for (int o = 16; o; o >>= 1) {
                x1 += __shfl_xor_sync(0xffffffffu, x1, o);
                x2 += __shfl_xor_sync(0xffffffffu, x2, o);
            }
            if (lane == 0 && j < len) {
                int slot = fwd ? j : (len - 1 - j);
                if (fwd) {
                    sk1_s[slot] = -ALPHA * x1 + cb[j];
                } else {
                    sk1_s[slot] = -ALPHA * x1;
                    sv1_s[slot] = BETA * dpow[j] * x1;
                    if (dual) { sk2_s[slot] = -ALPHA * x2; sv2_s[slot] = BETA * dpow[j] * x2; }
                }
            }
        }
        __syncthreads();

        // stage B: rank updates from smem rows (coalesced)
        float w1 = 0.f, w2 = 0.f, o1 = 0.f, o2 = 0.f;
        #pragma unroll
        for (int s = 0; s < CH; s++) {
            float kk = Kb[s*DK + tid];
            w1 += sk1_s[s] * kk;
            if (dual) w2 += sk2_s[s] * kk;
            if (hasV) {
                float vv = Vb[s*DK + tid];
                o1 += sv1_s[s] * vv;
                if (dual) o2 += sv2_s[s] * vv;
            }
        }
        out1 += o1; out2 += o2;
        float dl = dpow[len];
        a1 = dl * (a1 + w1);
        if (dual) a2 = dl * (a2 + w2);
        a1_s[tid] = a1;
        if (dual) a2_s[tid] = a2;
    }

    if (bid == 0) {
        // wait for blocks 1,2 then combine
        if (tid == 0) {
            while (*((volatile int*)&g_done) < 2) { }
        }
        __syncthreads();
        float r1  = __ldcg(&g_res[1*DK + tid]);   // para recall (q probe)
        float r2  = __ldcg(&g_res[2*DK + tid]);   // doc_v
        float dkv = __ldcg(&g_res[3*DK + tid]);   // doc_k
        float ssd = bred256(dkv*dkv, red);
        float dot = bred256(qv*dkv, red);
        float coef = dot * s_inv / fmaxf(sqrtf(ssd), EPSN);
        out[tid] = 0.2f*out1 + 0.3f*r1 + 0.5f*(BETA*coef)*r2;
    } else {
        if (bid == 1) { g_res[1*DK + tid] = out1; g_res[2*DK + tid] = out2; }
        else          { g_res[3*DK + tid] = a1; }
        __threadfence();
        __syncthreads();
        if (tid == 0) atomicAdd(&g_done, 1);
    }
}

// ---------------- launcher ----------------
extern "C" void kernel_launch(void* const* d_in, const int* in_sizes, int n_in,
                              void* d_out, int out_size)
{
    const float* emb = (const float*)d_in[0];
    const float* q   = (const float*)d_in[1];
    const float* Wk  = (const float*)d_in[2];
    const float* bk  = (const float*)d_in[3];
    const float* Wv  = (const float*)d_in[4];
    const float* bv  = (const float*)d_in[5];
    // d_in[6..8] = zero initial memories (collapsed analytically)

    int T = in_sizes[0] / DEMB;     // 1000
    int P = T / 5;                  // 200
    int nchS = (T + CH - 1) / CH;   // 32
    int nchP = (P + CH - 1) / CH;   // 7

    cudaFuncSetAttribute(k_prep, cudaFuncAttributeMaxDynamicSharedMemorySize, 16640*4);
    cudaFuncSetAttribute(k_scan, cudaFuncAttributeMaxDynamicSharedMemorySize, BUFS*BUF_FLOATS*4);

    k_kv  <<<(T + 7)/8, 256>>>(emb, Wk, bk, Wv, bv, T);
    k_prep<<<nchS + nchP, 256, 16640*4>>>(T, P, nchS, nchP);
    k_scan<<<3, 256, BUFS*BUF_FLOATS*4>>>(q, (float*)d_out, T, P, nchS, nchP);
}

// round 4
// speedup vs baseline: 1.6615x; 1.6615x over previous
#include <cuda_runtime.h>
#include <math.h>
#include <stdint.h>

#define DK 256
#define DEMB 768
#define CH 32
#define TMAX 1000
#define PMAX 200
#define NCHS_MAX ((TMAX + CH - 1) / CH)   // 32
#define NCHP_MAX ((PMAX + CH - 1) / CH)   // 7

#define S_DECAY 0.95f
#define P_DECAY 0.99f
#define ALPHA   0.1f
#define BETA    1.0f
#define EPSN    1e-12f

// ---------------- device scratch ----------------
__device__ float g_K [TMAX*DK];   // K, normalized in place by k_norm
__device__ float g_V [TMAX*DK];
__device__ float g_PK[PMAX*DK];   // PK, normalized in place
__device__ float g_PV[PMAX*DK];
__device__ float g_Pm[PMAX];      // row means of PV
__device__ float g_W[(NCHS_MAX + 2*NCHP_MAX)*CH*DK];
__device__ float g_c[NCHP_MAX*CH];
__device__ float g_res[4*DK];

// ---------------- helpers ----------------
__device__ __forceinline__ unsigned long long pack2(float lo, float hi) {
    unsigned long long r;
    asm("mov.b64 %0, {%1, %2};" : "=l"(r) : "f"(lo), "f"(hi));
    return r;
}
__device__ __forceinline__ unsigned long long fma2(unsigned long long a,
                                                   unsigned long long b,
                                                   unsigned long long c) {
    unsigned long long d;
    asm("fma.rn.f32x2 %0, %1, %2, %3;" : "=l"(d) : "l"(a), "l"(b), "l"(c));
    return d;
}
__device__ __forceinline__ void unpack2(unsigned long long v, float& lo, float& hi) {
    asm("mov.b64 {%0, %1}, %2;" : "=f"(lo), "=f"(hi) : "l"(v));
}
__device__ __forceinline__ uint32_t smem_u32(const void* p) {
    uint32_t a;
    asm("{ .reg .u64 t; cvta.to.shared.u64 t, %1; cvt.u32.u64 %0, t; }" : "=r"(a) : "l"(p));
    return a;
}
__device__ __forceinline__ void mbar_init(uint32_t a, uint32_t n) {
    asm volatile("mbarrier.init.shared.b64 [%0], %1;" :: "r"(a), "r"(n) : "memory");
}
__device__ __forceinline__ void mbar_expect(uint32_t a, uint32_t bytes) {
    asm volatile("mbarrier.arrive.expect_tx.shared.b64 _, [%0], %1;" :: "r"(a), "r"(bytes) : "memory");
}
__device__ __forceinline__ void bulk_g2s(uint32_t dst, const void* src, uint32_t bytes, uint32_t mbar) {
    asm volatile("cp.async.bulk.shared::cluster.global.mbarrier::complete_tx::bytes [%0], [%1], %2, [%3];"
                 :: "r"(dst), "l"(src), "r"(bytes), "r"(mbar) : "memory");
}
__device__ __forceinline__ void mbar_wait(uint32_t a, uint32_t parity) {
    asm volatile(
        "{\n\t.reg .pred P;\n"
        "W_%=:\n\t"
        "mbarrier.try_wait.parity.acquire.cta.shared::cta.b64 P, [%0], %1, 0x989680;\n\t"
        "@P bra.uni D_%=;\n\t"
        "bra.uni W_%=;\n"
        "D_%=:\n\t}"
        :: "r"(a), "r"(parity) : "memory");
}

// ---------------- kernel 1: K/V projection, TMA double-buffered weights ----------------
// 8 rows per block. Weights staged 32 e-rows at a time (Wk 32KB + Wv 32KB per stage).
#define ETILE 32
#define NSTAGE (DEMB / ETILE)     // 24
__global__ void __launch_bounds__(256) k_kv(const float* __restrict__ emb,
                     const float* __restrict__ Wk, const float* __restrict__ bk,
                     const float* __restrict__ Wv, const float* __restrict__ bv,
                     int T)
{
    extern __shared__ __align__(16) float wbuf[];      // 2 × (32×256 K + 32×256 V) floats
    __shared__ __align__(16) float est[DEMB*12];       // transposed emb tile (stride 12)
    __shared__ __align__(8) unsigned long long mb[2];

    const int tid = threadIdx.x;
    const int r0  = blockIdx.x * 8;
    const int rows = min(8, T - r0);
    const uint32_t wbufb = smem_u32(wbuf);

    for (int idx = tid; idx < 8*DEMB; idx += 256) {
        int r = idx / DEMB, e = idx - r*DEMB;
        est[e*12 + r] = (r < rows) ? emb[(r0 + r)*DEMB + e] : 0.f;
    }
    if (tid == 0) { mbar_init(smem_u32(&mb[0]), 1); mbar_init(smem_u32(&mb[1]), 1); }
    __syncthreads();

    auto issue = [&](int s) {
        uint32_t mba = smem_u32(&mb[s & 1]);
        uint32_t dst = wbufb + (uint32_t)(s & 1) * 65536u;
        mbar_expect(mba, 65536u);
        bulk_g2s(dst,           Wk + s*ETILE*DK, 32768u, mba);
        bulk_g2s(dst + 32768u,  Wv + s*ETILE*DK, 32768u, mba);
    };
    if (tid == 0) { issue(0); issue(1); }

    unsigned long long aK[4], aV[4];
    #pragma unroll
    for (int p = 0; p < 4; p++) { aK[p] = pack2(0.f, 0.f); aV[p] = pack2(0.f, 0.f); }

    for (int s = 0; s < NSTAGE; s++) {
        mbar_wait(smem_u32(&mb[s & 1]), (s >> 1) & 1);
        const float* Wks = wbuf + (s & 1) * 16384;
        const float* Wvs = Wks + 8192;
        const int e0 = s * ETILE;

        #pragma unroll 8
        for (int ee = 0; ee < ETILE; ee++) {
            float wk = Wks[ee*DK + tid];
            float wv = Wvs[ee*DK + tid];
            unsigned long long wk2 = pack2(wk, wk);
            unsigned long long wv2 = pack2(wv, wv);
            const float* ep = &est[(e0 + ee)*12];
            ulonglong2 p01 = *(const ulonglong2*)ep;
            ulonglong2 p23 = *(const ulonglong2*)(ep + 4);
            aK[0] = fma2(p01.x, wk2, aK[0]);  aV[0] = fma2(p01.x, wv2, aV[0]);
            aK[1] = fma2(p01.y, wk2, aK[1]);  aV[1] = fma2(p01.y, wv2, aV[1]);
            aK[2] = fma2(p23.x, wk2, aK[2]);  aV[2] = fma2(p23.x, wv2, aV[2]);
            aK[3] = fma2(p23.y, wk2, aK[3]);  aV[3] = fma2(p23.y, wv2, aV[3]);
        }
        __syncthreads();                 // all warps done with buffer (s&1)
        if (tid == 0 && s + 2 < NSTAGE) issue(s + 2);
    }

    float bkv = bk[tid], bvv = bv[tid];
    #pragma unroll
    for (int p = 0; p < 4; p++) {
        float k0,k1,v0,v1;
        unpack2(aK[p], k0, k1);
        unpack2(aV[p], v0, v1);
        int r = 2*p;
        if (r < rows)     { g_K[(r0+r  )*DK + tid] = k0 + bkv; g_V[(r0+r  )*DK + tid] = v0 + bvv; }
        if (r + 1 < rows) { g_K[(r0+r+1)*DK + tid] = k1 + bkv; g_V[(r0+r+1)*DK + tid] = v1 + bvv; }
    }
}

// ---------------- kernel 2: paragraph means + Pm ----------------
__global__ void k_para(int P)
{
    const int p = blockIdx.x, tid = threadIdx.x;
    float sk = 0.f, sv = 0.f;
    #pragma unroll
    for (int r = 0; r < 5; r++) {
        sk += g_K[(p*5 + r)*DK + tid];
        sv += g_V[(p*5 + r)*DK + tid];
    }
    sk *= 0.2f; sv *= 0.2f;
    g_PK[p*DK + tid] = sk;
    g_PV[p*DK + tid] = sv;

    __shared__ float red[8];
    float x = sv;
    #pragma unroll
    for (int o = 16; o; o >>= 1) x += __shfl_xor_sync(0xffffffffu, x, o);
    if ((tid & 31) == 0) red[tid >> 5] = x;
    __syncthreads();
    if (tid == 0) {
        float s = 0.f;
        #pragma unroll
        for (int w = 0; w < 8; w++) s += red[w];
        g_Pm[p] = s * (1.f/256.f);
    }
}

// ---------------- kernel 3: normalize K rows (and PK rows), in place ----------------
__global__ void k_norm(int T, int P)
{
    const int row = blockIdx.x, tid = threadIdx.x;
    float* base = (row < T) ? g_K : g_PK;
    const int r = (row < T) ? row : row - T;
    float v = base[r*DK + tid];
    float x = v * v;
    #pragma unroll
    for (int o = 16; o; o >>= 1) x += __shfl_xor_sync(0xffffffffu, x, o);
    __shared__ float red[8];
    __shared__ float s_inv;
    if ((tid & 31) == 0) red[tid >> 5] = x;
    __syncthreads();
    if (tid == 0) {
        float s = 0.f;
        #pragma unroll
        for (int w = 0; w < 8; w++) s += red[w];
        s_inv = 1.f / fmaxf(sqrtf(s), EPSN);
    }
    __syncthreads();
    base[r*DK + tid] = v * s_inv;
}

// ---------------- kernel 4: Gram + triangular inverse + W = T*K (+ fwd constants) --------
__global__ void __launch_bounds__(256) k_prep(int T, int P, int nchS, int nchP)
{
    __shared__ __align__(16) float ks[CH*260];
    __shared__ float Gs[CH*33];
    __shared__ __align__(16) float Ts[CH*36];
    __shared__ float fs[CH], lfs[CH];

    const int cid = blockIdx.x, tid = threadIdx.x;
    const int wid = tid >> 5, lane = tid & 31;

    int type, chunk, steps;
    const float* kdat;
    if (cid < nchS)              { type = 0; chunk = cid;             kdat = g_K;  steps = T; }
    else if (cid < nchS + nchP)  { type = 1; chunk = cid - nchS;      kdat = g_PK; steps = P; }
    else                         { type = 2; chunk = cid - nchS-nchP; kdat = g_PK; steps = P; }
    const int lo  = chunk * CH;
    const int len = min(CH, steps - lo);
    const bool bwd = (type <= 1);

    #pragma unroll
    for (int u = 0; u < 8; u++) {
        int id = tid + 256*u;
        int a = id >> 6, c4 = (id & 63) * 4;
        float4 v = make_float4(0.f, 0.f, 0.f, 0.f);
        if (a < len) v = *(const float4*)&kdat[(lo + a)*DK + c4];
        *(float4*)&ks[a*260 + c4] = v;
    }
    __syncthreads();

    {
        float acc[4] = {0.f, 0.f, 0.f, 0.f};
        #pragma unroll 8
        for (int i4 = 0; i4 < 64; i4++) {
            float4 own = *(const float4*)&ks[lane*260 + i4*4];
            #pragma unroll
            for (int s = 0; s < 4; s++) {
                float4 b = *(const float4*)&ks[(wid + 8*s)*260 + i4*4];
                acc[s] += own.x*b.x + own.y*b.y + own.z*b.z + own.w*b.w;
            }
        }
        #pragma unroll
        for (int s = 0; s < 4; s++) Gs[(wid + 8*s)*33 + lane] = acc[s];
    }
    __syncthreads();

    #pragma unroll
    for (int cc = 0; cc < 4; cc++) {
        int k = wid*4 + cc;
        float v = (lane == k) ? 1.f : 0.f;
        for (int i = 0; i < len; i++) {
            float vi = __shfl_sync(0xffffffffu, v, i);
            if (lane > i && lane < len) {
                float g = bwd ? Gs[(len-1-lane)*33 + (len-1-i)]
                              : Gs[lane*33 + i];
                v -= ALPHA * g * vi;
            }
        }
        Ts[lane*36 + k] = v;
    }
    __syncthreads();

    if (type == 2 && wid == 0) {
        float f = 0.f;
        if (lane < len) {
            float dp = 1.f;
            for (int i = 0; i <= lane; i++) dp *= (1.f / P_DECAY);
            f = BETA * dp * g_Pm[lo + lane];
        }
        fs[lane] = f;
        __syncwarp();
        float lf = 0.f;
        if (lane < len)
            for (int i = 0; i < lane; i++) lf += Gs[lane*33 + i] * fs[i];
        lfs[lane] = lf;
        __syncwarp();
        float e = 0.f;
        #pragma unroll 8
        for (int k2 = 0; k2 < CH; k2++) e += Ts[lane*36 + k2] * lfs[k2];
        g_c[chunk*CH + lane] = -ALPHA * e + f;
    }

    float ksv[CH];
    #pragma unroll
    for (int m = 0; m < CH; m++) {
        int rl = bwd ? (len - 1 - m) : m;
        ksv[m] = (m < len) ? ks[rl*260 + tid] : 0.f;
    }
    float* Wout = g_W + (size_t)cid * CH * DK;
    #pragma unroll
    for (int j = 0; j < CH; j++) {
        float acc2 = 0.f;
        #pragma unroll
        for (int m4 = 0; m4 < 8; m4++) {
            float4 t = *(const float4*)&Ts[j*36 + m4*4];
            acc2 += t.x*ksv[m4*4] + t.y*ksv[m4*4+1] + t.z*ksv[m4*4+2] + t.w*ksv[m4*4+3];
        }
        Wout[j*DK + tid] = acc2;
    }
}

// ---------------- kernel 5: chunked probe scans (4 concurrent blocks) ----------------
__global__ void __launch_bounds__(256) k_scan(const float* __restrict__ q,
                                              int T, int P, int nchS, int nchP)
{
    __shared__ float a_s[DK];
    __shared__ float sigk_s[CH], sigv_s[CH];
    __shared__ float dpow[CH+1];
    __shared__ float red[8];
    __shared__ float s_inv;

    const int bid = blockIdx.x, tid = threadIdx.x;
    const int wid = tid >> 5, lane = tid & 31;
    const bool fwd  = (bid == 3);
    const bool sent = (bid == 0);
    const float decay = sent ? S_DECAY : P_DECAY;
    const int nch   = sent ? nchS : nchP;
    const int steps = sent ? T : P;
    const float* Kd = sent ? g_K : g_PK;
    const float* Vd = sent ? g_V : g_PV;
    const int slot0 = sent ? 0 : (fwd ? (nchS + nchP) : nchS);

    if (tid == 0) {
        dpow[0] = 1.f;
        for (int i = 0; i < CH; i++) dpow[i+1] = dpow[i] * decay;
    }

    float a;
    if (bid <= 1) {
        float qv = q[tid];
        float x = qv * qv;
        #pragma unroll
        for (int o = 16; o; o >>= 1) x += __shfl_xor_sync(0xffffffffu, x, o);
        if (lane == 0) red[wid] = x;
        __syncthreads();
        if (tid == 0) {
            float s = 0.f;
            #pragma unroll
            for (int w = 0; w < 8; w++) s += red[w];
            s_inv = 1.f / fmaxf(sqrtf(s), EPSN);
        }
        __syncthreads();
        a = qv * s_inv;
    } else {
        a = (bid == 2) ? (1.f/256.f) : 0.f;
    }
    a_s[tid] = a;

    const int j0 = wid * 4;
    float wreg[4][8];
    float creg[4] = {0.f, 0.f, 0.f, 0.f};

    {
        int chunk = fwd ? 0 : (nch - 1);
        const float* Wp = g_W + (size_t)(slot0 + chunk) * CH * DK;
        #pragma unroll
        for (int r = 0; r < 4; r++)
            #pragma unroll
            for (int m = 0; m < 8; m++)
                wreg[r][m] = Wp[(j0 + r)*DK + lane + 32*m];
        if (fwd) {
            #pragma unroll
            for (int r = 0; r < 4; r++) creg[r] = g_c[chunk*CH + j0 + r];
        }
    }

    float outreg = 0.f;

    for (int c = 0; c < nch; c++) {
        const int chunk = fwd ? c : (nch - 1 - c);
        const int lo  = chunk * CH;
        const int len = min(CH, steps - lo);
        const int hi  = lo + len - 1;
        __syncthreads();

        float kreg[CH], vreg[CH];
        #pragma unroll
        for (int j = 0; j < CH; j++) {
            int row = fwd ? (lo + j) : (hi - j);
            row = max(0, min(row, steps - 1));
            kreg[j] = Kd[row*DK + tid];
            vreg[j] = fwd ? 0.f : Vd[row*DK + tid];
        }

        float av[8];
        #pragma unroll
        for (int m = 0; m < 8; m++) av[m] = a_s[lane + 32*m];
        float s[4];
        #pragma unroll
        for (int r = 0; r < 4; r++) {
            float t = 0.f;
            #pragma unroll
            for (int m = 0; m < 8; m++) t += wreg[r][m] * av[m];
            s[r] = t;
        }
        #pragma unroll
        for (int o = 16; o; o >>= 1)
            #pragma unroll
            for (int r = 0; r < 4; r++)
                s[r] += __shfl_xor_sync(0xffffffffu, s[r], o);
        if (lane == 0) {
            #pragma unroll
            for (int r = 0; r < 4; r++) {
                int j = j0 + r;
                float sk = 0.f, sv = 0.f;
                if (j < len) {
                    if (fwd) { sk = -ALPHA * s[r] + creg[r]; }
                    else     { sk = -ALPHA * s[r]; sv = BETA * dpow[j] * s[r]; }
                }
                sigk_s[j] = sk;
                sigv_s[j] = sv;
            }
        }

        if (c + 1 < nch) {
            int nchunk = fwd ? (c + 1) : (nch - 2 - c);
            const float* Wp = g_W + (size_t)(slot0 + nchunk) * CH * DK;
            #pragma unroll
            for (int r = 0; r < 4; r++)
                #pragma unroll
                for (int m = 0; m < 8; m++)
                    wreg[r][m] = Wp[(j0 + r)*DK + lane + 32*m];
            if (fwd) {
                #pragma unroll
                for (int r = 0; r < 4; r++) creg[r] = g_c[nchunk*CH + j0 + r];
            }
        }
        __syncthreads();

        float wsum = 0.f, osum = 0.f;
        #pragma unroll
        for (int j = 0; j < CH; j++) {
            wsum += sigk_s[j] * kreg[j];
            osum += sigv_s[j] * vreg[j];
        }
        outreg += osum;
        a = dpow[len] * (a + wsum);
        a_s[tid] = a;
    }

    if (bid < 3) g_res[bid*DK + tid] = outreg;
    else         g_res[3*DK + tid]   = a;
}

// ---------------- kernel 6: combine ----------------
__device__ __forceinline__ float bred256(float x, float* red)
{
    const int tid = threadIdx.x;
    #pragma unroll
    for (int o = 16; o; o >>= 1) x += __shfl_xor_sync(0xffffffffu, x, o);
    __syncthreads();
    if ((tid & 31) == 0) red[tid >> 5] = x;
    __syncthreads();
    float s = 0.f;
    #pragma unroll
    for (int w = 0; w < 8; w++) s += red[w];
    return s;
}

__global__ void k_final(const float* __restrict__ q, float* __restrict__ out)
{
    __shared__ float red[8];
    const int tid = threadIdx.x;
    float qv  = q[tid];
    float dkv = g_res[3*256 + tid];
    float ssq = bred256(qv*qv, red);
    float ssd = bred256(dkv*dkv, red);
    float dot = bred256(qv*dkv, red);
    float coef = dot / (fmaxf(sqrtf(ssq), EPSN) * fmaxf(sqrtf(ssd), EPSN));
    out[tid] = 0.2f*g_res[tid] + 0.3f*g_res[256 + tid]
             + 0.5f * (BETA * coef) * g_res[512 + tid];
}

// ---------------- launcher ----------------
extern "C" void kernel_launch(void* const* d_in, const int* in_sizes, int n_in,
                              void* d_out, int out_size)
{
    const float* emb = (const float*)d_in[0];
    const float* q   = (const float*)d_in[1];
    const float* Wk  = (const float*)d_in[2];
    const float* bk  = (const float*)d_in[3];
    const float* Wv  = (const float*)d_in[4];
    const float* bv  = (const float*)d_in[5];
    // d_in[6..8] = zero initial memories (collapsed analytically)

    int T = in_sizes[0] / DEMB;     // 1000
    int P = T / 5;                  // 200
    int nchS = (T + CH - 1) / CH;   // 32
    int nchP = (P + CH - 1) / CH;   // 7

    cudaFuncSetAttribute(k_kv, cudaFuncAttributeMaxDynamicSharedMemorySize, 131072);

    k_kv  <<<(T + 7)/8, 256, 131072>>>(emb, Wk, bk, Wv, bv, T);
    k_para<<<P, 256>>>(P);
    k_norm<<<T + P, 256>>>(T, P);
    k_prep<<<nchS + 2*nchP, 256>>>(T, P, nchS, nchP);
    k_scan<<<4, 256>>>(q, T, P, nchS, nchP);
    k_final<<<1, 256>>>(q, (float*)d_out);
}

// round 5
// speedup vs baseline: 1.6898x; 1.0171x over previous
#include <cuda_runtime.h>
#include <math.h>
#include <stdint.h>

#define DK 256
#define DEMB 768
#define CH 32
#define TMAX 1000
#define PMAX 200
#define NCHS_MAX ((TMAX + CH - 1) / CH)   // 32
#define NCHP_MAX ((PMAX + CH - 1) / CH)   // 7

#define S_DECAY 0.95f
#define P_DECAY 0.99f
#define ALPHA   0.1f
#define BETA    1.0f
#define EPSN    1e-12f

// ---------------- device scratch ----------------
__device__ float g_K [TMAX*DK];   // raw K (k_kv output)
__device__ float g_Kn[TMAX*DK];   // normalized K (prep output)
__device__ float g_V [TMAX*DK];   // raw V
__device__ float g_PK[PMAX*DK];   // normalized PK (prep output)
__device__ float g_PV[PMAX*DK];   // raw PV (prep output)
__device__ float g_W[(NCHS_MAX + 2*NCHP_MAX)*CH*DK];
__device__ float g_c[NCHP_MAX*CH];
__device__ float g_res[4*DK];

// ---------------- helpers ----------------
__device__ __forceinline__ unsigned long long pack2(float lo, float hi) {
    unsigned long long r;
    asm("mov.b64 %0, {%1, %2};" : "=l"(r) : "f"(lo), "f"(hi));
    return r;
}
__device__ __forceinline__ unsigned long long fma2(unsigned long long a,
                                                   unsigned long long b,
                                                   unsigned long long c) {
    unsigned long long d;
    asm("fma.rn.f32x2 %0, %1, %2, %3;" : "=l"(d) : "l"(a), "l"(b), "l"(c));
    return d;
}
__device__ __forceinline__ void unpack2(unsigned long long v, float& lo, float& hi) {
    asm("mov.b64 {%0, %1}, %2;" : "=f"(lo), "=f"(hi) : "l"(v));
}
__device__ __forceinline__ uint32_t smem_u32(const void* p) {
    uint32_t a;
    asm("{ .reg .u64 t; cvta.to.shared.u64 t, %1; cvt.u32.u64 %0, t; }" : "=r"(a) : "l"(p));
    return a;
}
__device__ __forceinline__ void mbar_init(uint32_t a, uint32_t n) {
    asm volatile("mbarrier.init.shared.b64 [%0], %1;" :: "r"(a), "r"(n) : "memory");
}
__device__ __forceinline__ void mbar_expect(uint32_t a, uint32_t bytes) {
    asm volatile("mbarrier.arrive.expect_tx.shared.b64 _, [%0], %1;" :: "r"(a), "r"(bytes) : "memory");
}
__device__ __forceinline__ void bulk_g2s(uint32_t dst, const void* src, uint32_t bytes, uint32_t mbar) {
    asm volatile("cp.async.bulk.shared::cluster.global.mbarrier::complete_tx::bytes [%0], [%1], %2, [%3];"
                 :: "r"(dst), "l"(src), "r"(bytes), "r"(mbar) : "memory");
}
__device__ __forceinline__ void mbar_wait(uint32_t a, uint32_t parity) {
    asm volatile(
        "{\n\t.reg .pred P;\n"
        "W_%=:\n\t"
        "mbarrier.try_wait.parity.acquire.cta.shared::cta.b64 P, [%0], %1, 0x989680;\n\t"
        "@P bra.uni D_%=;\n\t"
        "bra.uni W_%=;\n"
        "D_%=:\n\t}"
        :: "r"(a), "r"(parity) : "memory");
}

// ---------------- kernel 1: K/V projection, TMA double-buffered weights ----------------
#define ETILE 32
#define NSTAGE (DEMB / ETILE)     // 24
__global__ void __launch_bounds__(256, 1) k_kv(const float* __restrict__ emb,
                     const float* __restrict__ Wk, const float* __restrict__ bk,
                     const float* __restrict__ Wv, const float* __restrict__ bv,
                     int T)
{
    extern __shared__ __align__(16) float wbuf[];      // 2 × (32×256 K + 32×256 V)
    __shared__ __align__(16) float est[DEMB*12];       // transposed emb tile (stride 12)
    __shared__ __align__(8) unsigned long long mb[2];

    const int tid = threadIdx.x;
    const int r0  = blockIdx.x * 8;
    const int rows = min(8, T - r0);
    const uint32_t wbufb = smem_u32(wbuf);

    for (int idx = tid; idx < 8*DEMB; idx += 256) {
        int r = idx / DEMB, e = idx - r*DEMB;
        est[e*12 + r] = (r < rows) ? emb[(r0 + r)*DEMB + e] : 0.f;
    }
    if (tid == 0) { mbar_init(smem_u32(&mb[0]), 1); mbar_init(smem_u32(&mb[1]), 1); }
    __syncthreads();

    auto issue = [&](int s) {
        uint32_t mba = smem_u32(&mb[s & 1]);
        uint32_t dst = wbufb + (uint32_t)(s & 1) * 65536u;
        mbar_expect(mba, 65536u);
        bulk_g2s(dst,           Wk + s*ETILE*DK, 32768u, mba);
        bulk_g2s(dst + 32768u,  Wv + s*ETILE*DK, 32768u, mba);
    };
    if (tid == 0) { issue(0); issue(1); }

    unsigned long long aK[4], aV[4];
    #pragma unroll
    for (int p = 0; p < 4; p++) { aK[p] = pack2(0.f, 0.f); aV[p] = pack2(0.f, 0.f); }

    for (int s = 0; s < NSTAGE; s++) {
        mbar_wait(smem_u32(&mb[s & 1]), (s >> 1) & 1);
        const float* Wks = wbuf + (s & 1) * 16384;
        const float* Wvs = Wks + 8192;
        const int e0 = s * ETILE;

        #pragma unroll 16
        for (int ee = 0; ee < ETILE; ee++) {
            float wk = Wks[ee*DK + tid];
            float wv = Wvs[ee*DK + tid];
            unsigned long long wk2 = pack2(wk, wk);
            unsigned long long wv2 = pack2(wv, wv);
            const float* ep = &est[(e0 + ee)*12];
            ulonglong2 p01 = *(const ulonglong2*)ep;
            ulonglong2 p23 = *(const ulonglong2*)(ep + 4);
            aK[0] = fma2(p01.x, wk2, aK[0]);  aV[0] = fma2(p01.x, wv2, aV[0]);
            aK[1] = fma2(p01.y, wk2, aK[1]);  aV[1] = fma2(p01.y, wv2, aV[1]);
            aK[2] = fma2(p23.x, wk2, aK[2]);  aV[2] = fma2(p23.x, wv2, aV[2]);
            aK[3] = fma2(p23.y, wk2, aK[3]);  aV[3] = fma2(p23.y, wv2, aV[3]);
        }
        __syncthreads();
        if (tid == 0 && s + 2 < NSTAGE) issue(s + 2);
    }

    float bkv = bk[tid], bvv = bv[tid];
    #pragma unroll
    for (int p = 0; p < 4; p++) {
        float k0,k1,v0,v1;
        unpack2(aK[p], k0, k1);
        unpack2(aV[p], v0, v1);
        int r = 2*p;
        if (r < rows)     { g_K[(r0+r  )*DK + tid] = k0 + bkv; g_V[(r0+r  )*DK + tid] = v0 + bvv; }
        if (r + 1 < rows) { g_K[(r0+r+1)*DK + tid] = k1 + bkv; g_V[(r0+r+1)*DK + tid] = v1 + bvv; }
    }
}

// ---------------- kernel 2: fused means + norm + Gram + inverse + W + constants --------
// blocks [0,nchS): sentence bwd; [nchS,nchS+nchP): para bwd; [nchS+nchP,+nchP): para fwd.
__global__ void __launch_bounds__(256) k_prep(int T, int P, int nchS, int nchP)
{
    extern __shared__ __align__(16) float dyn[];
    float* ks = dyn;            // 32*260
    float* vs = dyn + 8320;     // 32*260 (para only)
    __shared__ float Gs[CH*33];
    __shared__ __align__(16) float Ts[CH*36];
    __shared__ float Pm[CH];
    __shared__ float fs[CH], lfs[CH];

    const int cid = blockIdx.x, tid = threadIdx.x;
    const int wid = tid >> 5, lane = tid & 31;

    int type, chunk, steps;
    if (cid < nchS)              { type = 0; chunk = cid;               steps = T; }
    else if (cid < nchS + nchP)  { type = 1; chunk = cid - nchS;        steps = P; }
    else                         { type = 2; chunk = cid - nchS - nchP; steps = P; }
    const int lo  = chunk * CH;
    const int len = min(CH, steps - lo);
    const bool bwd = (type <= 1);
    const bool isPara = (type >= 1);

    if (!isPara) {
        // load raw K chunk, zero-pad
        #pragma unroll
        for (int u = 0; u < 8; u++) {
            int id = tid + 256*u;
            int a = id >> 6, c4 = (id & 63) * 4;
            float4 v = make_float4(0.f, 0.f, 0.f, 0.f);
            if (a < len) v = *(const float4*)&g_K[(lo + a)*DK + c4];
            *(float4*)&ks[a*260 + c4] = v;
        }
    } else {
        // PK/PV = 5-group means of raw K/V
        #pragma unroll
        for (int g = 0; g < 8; g++) {
            int r  = (tid >> 6) + 4*g;
            int c4 = (tid & 63) * 4;
            float4 ak = make_float4(0.f,0.f,0.f,0.f);
            float4 av = make_float4(0.f,0.f,0.f,0.f);
            if (r < len) {
                #pragma unroll
                for (int i = 0; i < 5; i++) {
                    float4 kk = *(const float4*)&g_K[((lo + r)*5 + i)*DK + c4];
                    float4 vv = *(const float4*)&g_V[((lo + r)*5 + i)*DK + c4];
                    ak.x += kk.x; ak.y += kk.y; ak.z += kk.z; ak.w += kk.w;
                    av.x += vv.x; av.y += vv.y; av.z += vv.z; av.w += vv.w;
                }
                ak.x *= 0.2f; ak.y *= 0.2f; ak.z *= 0.2f; ak.w *= 0.2f;
                av.x *= 0.2f; av.y *= 0.2f; av.z *= 0.2f; av.w *= 0.2f;
                if (type == 1) *(float4*)&g_PV[(lo + r)*DK + c4] = av;  // sole writer
            }
            *(float4*)&ks[r*260 + c4] = ak;
            *(float4*)&vs[r*260 + c4] = av;
        }
    }
    __syncthreads();

    // fwd block: Pm[r] = mean over dv of PV row
    if (type == 2) {
        #pragma unroll
        for (int rr = 0; rr < 4; rr++) {
            int r = wid*4 + rr;
            float s = 0.f;
            #pragma unroll
            for (int m = 0; m < 8; m++) s += vs[r*260 + lane + 32*m];
            #pragma unroll
            for (int o = 16; o; o >>= 1) s += __shfl_xor_sync(0xffffffffu, s, o);
            if (lane == 0) Pm[r] = s * (1.f/256.f);
        }
    }

    // normalize rows in smem; write g_Kn (sentence) / g_PK (para-bwd only)
    {
        float* gout = isPara ? g_PK : g_Kn;
        const bool wr = (type != 2);
        #pragma unroll
        for (int rr = 0; rr < 4; rr++) {
            int r = wid*4 + rr;
            float v[8]; float s = 0.f;
            #pragma unroll
            for (int m = 0; m < 8; m++) { v[m] = ks[r*260 + lane + 32*m]; s += v[m]*v[m]; }
            #pragma unroll
            for (int o = 16; o; o >>= 1) s += __shfl_xor_sync(0xffffffffu, s, o);
            float rinv = 1.f / fmaxf(sqrtf(s), EPSN);
            #pragma unroll
            for (int m = 0; m < 8; m++) {
                float nv = v[m] * rinv;
                ks[r*260 + lane + 32*m] = nv;
                if (wr && r < len) gout[(lo + r)*DK + lane + 32*m] = nv;
            }
        }
    }
    __syncthreads();

    // Gram
    {
        float acc[4] = {0.f, 0.f, 0.f, 0.f};
        #pragma unroll 8
        for (int i4 = 0; i4 < 64; i4++) {
            float4 own = *(const float4*)&ks[lane*260 + i4*4];
            #pragma unroll
            for (int s = 0; s < 4; s++) {
                float4 b = *(const float4*)&ks[(wid + 8*s)*260 + i4*4];
                acc[s] += own.x*b.x + own.y*b.y + own.z*b.z + own.w*b.w;
            }
        }
        #pragma unroll
        for (int s = 0; s < 4; s++) Gs[(wid + 8*s)*33 + lane] = acc[s];
    }
    __syncthreads();

    // triangular inverse of (I + alpha*L) in scan order
    #pragma unroll
    for (int cc = 0; cc < 4; cc++) {
        int k = wid*4 + cc;
        float v = (lane == k) ? 1.f : 0.f;
        for (int i = 0; i < len; i++) {
            float vi = __shfl_sync(0xffffffffu, v, i);
            if (lane > i && lane < len) {
                float g = bwd ? Gs[(len-1-lane)*33 + (len-1-i)]
                              : Gs[lane*33 + i];
                v -= ALPHA * g * vi;
            }
        }
        Ts[lane*36 + k] = v;
    }
    __syncthreads();

    // fwd constants: c = -alpha * T_f (L f) + f, f_j = beta d^-(j+1) Pm_j
    if (type == 2 && wid == 0) {
        float f = 0.f;
        if (lane < len) {
            float dp = 1.f;
            for (int i = 0; i <= lane; i++) dp *= (1.f / P_DECAY);
            f = BETA * dp * Pm[lane];
        }
        fs[lane] = f;
        __syncwarp();
        float lf = 0.f;
        if (lane < len)
            for (int i = 0; i < lane; i++) lf += Gs[lane*33 + i] * fs[i];
        lfs[lane] = lf;
        __syncwarp();
        float e = 0.f;
        #pragma unroll 8
        for (int k2 = 0; k2 < CH; k2++) e += Ts[lane*36 + k2] * lfs[k2];
        g_c[chunk*CH + lane] = -ALPHA * e + f;
    }

    // W = T * K-chunk (rows in scan order); thread = column tid
    float ksv[CH];
    #pragma unroll
    for (int m = 0; m < CH; m++) {
        int rl = bwd ? (len - 1 - m) : m;
        ksv[m] = (m < len) ? ks[rl*260 + tid] : 0.f;
    }
    float* Wout = g_W + (size_t)cid * CH * DK;
    #pragma unroll
    for (int j = 0; j < CH; j++) {
        float acc2 = 0.f;
        #pragma unroll
        for (int m4 = 0; m4 < 8; m4++) {
            float4 t = *(const float4*)&Ts[j*36 + m4*4];
            acc2 += t.x*ksv[m4*4] + t.y*ksv[m4*4+1] + t.z*ksv[m4*4+2] + t.w*ksv[m4*4+3];
        }
        Wout[j*DK + tid] = acc2;
    }
}

// ---------------- kernel 3: chunked probe scans (4 concurrent blocks) ----------------
__global__ void __launch_bounds__(256) k_scan(const float* __restrict__ q,
                                              int T, int P, int nchS, int nchP)
{
    __shared__ float a_s[DK];
    __shared__ float sigk_s[CH], sigv_s[CH];
    __shared__ float dpow[CH+1];
    __shared__ float red[8];
    __shared__ float s_inv;

    const int bid = blockIdx.x, tid = threadIdx.x;
    const int wid = tid >> 5, lane = tid & 31;
    const bool fwd  = (bid == 3);
    const bool sent = (bid == 0);
    const float decay = sent ? S_DECAY : P_DECAY;
    const int nch   = sent ? nchS : nchP;
    const int steps = sent ? T : P;
    const float* Kd = sent ? g_Kn : g_PK;
    const float* Vd = sent ? g_V  : g_PV;
    const int slot0 = sent ? 0 : (fwd ? (nchS + nchP) : nchS);

    if (tid == 0) {
        dpow[0] = 1.f;
        for (int i = 0; i < CH; i++) dpow[i+1] = dpow[i] * decay;
    }

    float a;
    if (bid <= 1) {
        float qv = q[tid];
        float x = qv * qv;
        #pragma unroll
        for (int o = 16; o; o >>= 1) x += __shfl_xor_sync(0xffffffffu, x, o);
        if (lane == 0) red[wid] = x;
        __syncthreads();
        if (tid == 0) {
            float s = 0.f;
            #pragma unroll
            for (int w = 0; w < 8; w++) s += red[w];
            s_inv = 1.f / fmaxf(sqrtf(s), EPSN);
        }
        __syncthreads();
        a = qv * s_inv;
    } else {
        a = (bid == 2) ? (1.f/256.f) : 0.f;
    }
    a_s[tid] = a;

    const int j0 = wid * 4;
    float wreg[4][8];
    float creg[4] = {0.f, 0.f, 0.f, 0.f};

    {
        int chunk = fwd ? 0 : (nch - 1);
        const float* Wp = g_W + (size_t)(slot0 + chunk) * CH * DK;
        #pragma unroll
        for (int r = 0; r < 4; r++)
            #pragma unroll
            for (int m = 0; m < 8; m++)
                wreg[r][m] = Wp[(j0 + r)*DK + lane + 32*m];
        if (fwd) {
            #pragma unroll
            for (int r = 0; r < 4; r++) creg[r] = g_c[chunk*CH + j0 + r];
        }
    }

    float outreg = 0.f;

    for (int c = 0; c < nch; c++) {
        const int chunk = fwd ? c : (nch - 1 - c);
        const int lo  = chunk * CH;
        const int len = min(CH, steps - lo);
        const int hi  = lo + len - 1;
        __syncthreads();

        float kreg[CH], vreg[CH];
        #pragma unroll
        for (int j = 0; j < CH; j++) {
            int row = fwd ? (lo + j) : (hi - j);
            row = max(0, min(row, steps - 1));
            kreg[j] = Kd[row*DK + tid];
            vreg[j] = fwd ? 0.f : Vd[row*DK + tid];
        }

        float av[8];
        #pragma unroll
        for (int m = 0; m < 8; m++) av[m] = a_s[lane + 32*m];
        float s[4];
        #pragma unroll
        for (int r = 0; r < 4; r++) {
            float t = 0.f;
            #pragma unroll
            for (int m = 0; m < 8; m++) t += wreg[r][m] * av[m];
            s[r] = t;
        }
        #pragma unroll
        for (int o = 16; o; o >>= 1)
            #pragma unroll
            for (int r = 0; r < 4; r++)
                s[r] += __shfl_xor_sync(0xffffffffu, s[r], o);
        if (lane == 0) {
            #pragma unroll
            for (int r = 0; r < 4; r++) {
                int j = j0 + r;
                float sk = 0.f, sv = 0.f;
                if (j < len) {
                    if (fwd) { sk = -ALPHA * s[r] + creg[r]; }
                    else     { sk = -ALPHA * s[r]; sv = BETA * dpow[j] * s[r]; }
                }
                sigk_s[j] = sk;
                sigv_s[j] = sv;
            }
        }

        if (c + 1 < nch) {
            int nchunk = fwd ? (c + 1) : (nch - 2 - c);
            const float* Wp = g_W + (size_t)(slot0 + nchunk) * CH * DK;
            #pragma unroll
            for (int r = 0; r < 4; r++)
                #pragma unroll
                for (int m = 0; m < 8; m++)
                    wreg[r][m] = Wp[(j0 + r)*DK + lane + 32*m];
            if (fwd) {
                #pragma unroll
                for (int r = 0; r < 4; r++) creg[r] = g_c[nchunk*CH + j0 + r];
            }
        }
        __syncthreads();

        float wsum = 0.f, osum = 0.f;
        #pragma unroll
        for (int j = 0; j < CH; j++) {
            wsum += sigk_s[j] * kreg[j];
            osum += sigv_s[j] * vreg[j];
        }
        outreg += osum;
        a = dpow[len] * (a + wsum);
        a_s[tid] = a;
    }

    if (bid < 3) g_res[bid*DK + tid] = outreg;
    else         g_res[3*DK + tid]   = a;
}

// ---------------- kernel 4: combine ----------------
__device__ __forceinline__ float bred256(float x, float* red)
{
    const int tid = threadIdx.x;
    #pragma unroll
    for (int o = 16; o; o >>= 1) x += __shfl_xor_sync(0xffffffffu, x, o);
    __syncthreads();
    if ((tid & 31) == 0) red[tid >> 5] = x;
    __syncthreads();
    float s = 0.f;
    #pragma unroll
    for (int w = 0; w < 8; w++) s += red[w];
    return s;
}

__global__ void k_final(const float* __restrict__ q, float* __restrict__ out)
{
    __shared__ float red[8];
    const int tid = threadIdx.x;
    float qv  = q[tid];
    float dkv = g_res[3*256 + tid];
    float ssq = bred256(qv*qv, red);
    float ssd = bred256(dkv*dkv, red);
    float dot = bred256(qv*dkv, red);
    float coef = dot / (fmaxf(sqrtf(ssq), EPSN) * fmaxf(sqrtf(ssd), EPSN));
    out[tid] = 0.2f*g_res[tid] + 0.3f*g_res[256 + tid]
             + 0.5f * (BETA * coef) * g_res[512 + tid];
}

// ---------------- launcher ----------------
extern "C" void kernel_launch(void* const* d_in, const int* in_sizes, int n_in,
                              void* d_out, int out_size)
{
    const float* emb = (const float*)d_in[0];
    const float* q   = (const float*)d_in[1];
    const float* Wk  = (const float*)d_in[2];
    const float* bk  = (const float*)d_in[3];
    const float* Wv  = (const float*)d_in[4];
    const float* bv  = (const float*)d_in[5];
    // d_in[6..8] = zero initial memories (collapsed analytically)

    int T = in_sizes[0] / DEMB;     // 1000
    int P = T / 5;                  // 200
    int nchS = (T + CH - 1) / CH;   // 32
    int nchP = (P + CH - 1) / CH;   // 7

    cudaFuncSetAttribute(k_kv, cudaFuncAttributeMaxDynamicSharedMemorySize, 131072);
    cudaFuncSetAttribute(k_prep, cudaFuncAttributeMaxDynamicSharedMemorySize, 16640*4);

    k_kv  <<<(T + 7)/8, 256, 131072>>>(emb, Wk, bk, Wv, bv, T);
    k_prep<<<nchS + 2*nchP, 256, 16640*4>>>(T, P, nchS, nchP);
    k_scan<<<4, 256>>>(q, T, P, nchS, nchP);
    k_final<<<1, 256>>>(q, (float*)d_out);
}

// round 6
// speedup vs baseline: 1.6940x; 1.0025x over previous
#include <cuda_runtime.h>
#include <math.h>
#include <stdint.h>

#define DK 256
#define DEMB 768
#define CH 32
#define TMAX 1000
#define PMAX 200
#define NCHS_MAX ((TMAX + CH - 1) / CH)   // 32
#define NCHP_MAX ((PMAX + CH - 1) / CH)   // 7

#define S_DECAY 0.95f
#define P_DECAY 0.99f
#define ALPHA   0.1f
#define BETA    1.0f
#define EPSN    1e-12f

// ---------------- device scratch ----------------
__device__ float g_K [TMAX*DK];   // raw K (k_kv output)
__device__ float g_Kn[TMAX*DK];   // normalized K (prep output)
__device__ float g_V [TMAX*DK];   // raw V
__device__ float g_PK[PMAX*DK];   // normalized PK (prep output)
__device__ float g_PV[PMAX*DK];   // raw PV (prep output)
__device__ float g_W[(NCHS_MAX + 2*NCHP_MAX)*CH*DK];
__device__ float g_c[NCHP_MAX*CH];
__device__ float g_res[4*DK];

// ---------------- helpers ----------------
__device__ __forceinline__ unsigned long long pack2(float lo, float hi) {
    unsigned long long r;
    asm("mov.b64 %0, {%1, %2};" : "=l"(r) : "f"(lo), "f"(hi));
    return r;
}
__device__ __forceinline__ unsigned long long fma2(unsigned long long a,
                                                   unsigned long long b,
                                                   unsigned long long c) {
    unsigned long long d;
    asm("fma.rn.f32x2 %0, %1, %2, %3;" : "=l"(d) : "l"(a), "l"(b), "l"(c));
    return d;
}
__device__ __forceinline__ void unpack2(unsigned long long v, float& lo, float& hi) {
    asm("mov.b64 {%0, %1}, %2;" : "=f"(lo), "=f"(hi) : "l"(v));
}
__device__ __forceinline__ uint32_t smem_u32(const void* p) {
    uint32_t a;
    asm("{ .reg .u64 t; cvta.to.shared.u64 t, %1; cvt.u32.u64 %0, t; }" : "=r"(a) : "l"(p));
    return a;
}
__device__ __forceinline__ void mbar_init(uint32_t a, uint32_t n) {
    asm volatile("mbarrier.init.shared.b64 [%0], %1;" :: "r"(a), "r"(n) : "memory");
}
__device__ __forceinline__ void mbar_expect(uint32_t a, uint32_t bytes) {
    asm volatile("mbarrier.arrive.expect_tx.shared.b64 _, [%0], %1;" :: "r"(a), "r"(bytes) : "memory");
}
__device__ __forceinline__ void bulk_g2s(uint32_t dst, const void* src, uint32_t bytes, uint32_t mbar) {
    asm volatile("cp.async.bulk.shared::cluster.global.mbarrier::complete_tx::bytes [%0], [%1], %2, [%3];"
                 :: "r"(dst), "l"(src), "r"(bytes), "r"(mbar) : "memory");
}
__device__ __forceinline__ void mbar_wait(uint32_t a, uint32_t parity) {
    asm volatile(
        "{\n\t.reg .pred P;\n"
        "W_%=:\n\t"
        "mbarrier.try_wait.parity.acquire.cta.shared::cta.b64 P, [%0], %1, 0x989680;\n\t"
        "@P bra.uni D_%=;\n\t"
        "bra.uni W_%=;\n"
        "D_%=:\n\t}"
        :: "r"(a), "r"(parity) : "memory");
}

// ---------------- kernel 1: K/V projection ----------------
// Stage-rotated, triple-buffered TMA weight streaming. Block b starts at stage b%24
// so concurrent blocks touch disjoint L2 address ranges (no LTS lockstep hotspot).
#define ETILE 32
#define NSTAGE (DEMB / ETILE)     // 24
#define NBUF 3
#define WBUF_FLOATS (ETILE*DK*2)  // 16384 floats = 64KB per buffer
#define EST_OFF (NBUF*WBUF_FLOATS)        // 49152
#define KV_DYN_BYTES ((EST_OFF + DEMB*8) * 4)   // 221184 B

__global__ void __launch_bounds__(256, 1) k_kv(const float* __restrict__ emb,
                     const float* __restrict__ Wk, const float* __restrict__ bk,
                     const float* __restrict__ Wv, const float* __restrict__ bv,
                     int T)
{
    extern __shared__ __align__(16) float dynkv[];
    float* wbuf = dynkv;                 // NBUF × 16384 floats
    float* est  = dynkv + EST_OFF;       // 768 × 8, stride 8 (reads are broadcast)
    __shared__ __align__(8) unsigned long long mb[NBUF];

    const int tid = threadIdx.x;
    const int r0  = blockIdx.x * 8;
    const int rows = min(8, T - r0);
    const uint32_t wbufb = smem_u32(wbuf);
    const int s0 = blockIdx.x % NSTAGE;   // rotation offset

    for (int idx = tid; idx < 8*DEMB; idx += 256) {
        int e = idx >> 3, r = idx & 7;
        est[e*8 + r] = (r < rows) ? emb[(r0 + r)*DEMB + e] : 0.f;
    }
    if (tid == 0) {
        #pragma unroll
        for (int i = 0; i < NBUF; i++) mbar_init(smem_u32(&mb[i]), 1);
    }
    __syncthreads();

    auto issue = [&](int i) {            // i = loop index; stage = (s0+i)%NSTAGE
        int s = s0 + i; if (s >= NSTAGE) s -= NSTAGE;
        int buf = i % NBUF;
        uint32_t mba = smem_u32(&mb[buf]);
        uint32_t dst = wbufb + (uint32_t)buf * (WBUF_FLOATS*4u);
        mbar_expect(mba, WBUF_FLOATS*4u);
        bulk_g2s(dst,           Wk + s*ETILE*DK, ETILE*DK*4u, mba);
        bulk_g2s(dst + ETILE*DK*4u, Wv + s*ETILE*DK, ETILE*DK*4u, mba);
    };
    if (tid == 0) { issue(0); issue(1); issue(2); }

    unsigned long long aK[4], aV[4];
    #pragma unroll
    for (int p = 0; p < 4; p++) { aK[p] = pack2(0.f, 0.f); aV[p] = pack2(0.f, 0.f); }

    for (int i = 0; i < NSTAGE; i++) {
        int s = s0 + i; if (s >= NSTAGE) s -= NSTAGE;
        mbar_wait(smem_u32(&mb[i % NBUF]), (i / NBUF) & 1);
        const float* Wks = wbuf + (i % NBUF) * WBUF_FLOATS;
        const float* Wvs = Wks + ETILE*DK;
        const int e0 = s * ETILE;

        #pragma unroll 16
        for (int ee = 0; ee < ETILE; ee++) {
            float wk = Wks[ee*DK + tid];
            float wv = Wvs[ee*DK + tid];
            unsigned long long wk2 = pack2(wk, wk);
            unsigned long long wv2 = pack2(wv, wv);
            const float* ep = &est[(e0 + ee)*8];
            ulonglong2 p01 = *(const ulonglong2*)ep;
            ulonglong2 p23 = *(const ulonglong2*)(ep + 4);
            aK[0] = fma2(p01.x, wk2, aK[0]);  aV[0] = fma2(p01.x, wv2, aV[0]);
            aK[1] = fma2(p01.y, wk2, aK[1]);  aV[1] = fma2(p01.y, wv2, aV[1]);
            aK[2] = fma2(p23.x, wk2, aK[2]);  aV[2] = fma2(p23.x, wv2, aV[2]);
            aK[3] = fma2(p23.y, wk2, aK[3]);  aV[3] = fma2(p23.y, wv2, aV[3]);
        }
        __syncthreads();                // all warps done with buffer i%NBUF
        if (tid == 0 && i + NBUF < NSTAGE) issue(i + NBUF);
    }

    float bkv = bk[tid], bvv = bv[tid];
    #pragma unroll
    for (int p = 0; p < 4; p++) {
        float k0,k1,v0,v1;
        unpack2(aK[p], k0, k1);
        unpack2(aV[p], v0, v1);
        int r = 2*p;
        if (r < rows)     { g_K[(r0+r  )*DK + tid] = k0 + bkv; g_V[(r0+r  )*DK + tid] = v0 + bvv; }
        if (r + 1 < rows) { g_K[(r0+r+1)*DK + tid] = k1 + bkv; g_V[(r0+r+1)*DK + tid] = v1 + bvv; }
    }
}

// ---------------- kernel 2: fused means + norm + Gram + inverse + W + constants --------
__global__ void __launch_bounds__(256) k_prep(int T, int P, int nchS, int nchP)
{
    extern __shared__ __align__(16) float dyn[];
    float* ks = dyn;            // 32*260
    float* vs = dyn + 8320;     // 32*260 (para only)
    __shared__ float Gs[CH*33];
    __shared__ __align__(16) float Ts[CH*36];
    __shared__ float Pm[CH];
    __shared__ float fs[CH], lfs[CH];

    const int cid = blockIdx.x, tid = threadIdx.x;
    const int wid = tid >> 5, lane = tid & 31;

    int type, chunk, steps;
    if (cid < nchS)              { type = 0; chunk = cid;               steps = T; }
    else if (cid < nchS + nchP)  { type = 1; chunk = cid - nchS;        steps = P; }
    else                         { type = 2; chunk = cid - nchS - nchP; steps = P; }
    const int lo  = chunk * CH;
    const int len = min(CH, steps - lo);
    const bool bwd = (type <= 1);
    const bool isPara = (type >= 1);

    if (!isPara) {
        #pragma unroll
        for (int u = 0; u < 8; u++) {
            int id = tid + 256*u;
            int a = id >> 6, c4 = (id & 63) * 4;
            float4 v = make_float4(0.f, 0.f, 0.f, 0.f);
            if (a < len) v = *(const float4*)&g_K[(lo + a)*DK + c4];
            *(float4*)&ks[a*260 + c4] = v;
        }
    } else {
        #pragma unroll
        for (int g = 0; g < 8; g++) {
            int r  = (tid >> 6) + 4*g;
            int c4 = (tid & 63) * 4;
            float4 ak = make_float4(0.f,0.f,0.f,0.f);
            float4 av = make_float4(0.f,0.f,0.f,0.f);
            if (r < len) {
                #pragma unroll
                for (int i = 0; i < 5; i++) {
                    float4 kk = *(const float4*)&g_K[((lo + r)*5 + i)*DK + c4];
                    float4 vv = *(const float4*)&g_V[((lo + r)*5 + i)*DK + c4];
                    ak.x += kk.x; ak.y += kk.y; ak.z += kk.z; ak.w += kk.w;
                    av.x += vv.x; av.y += vv.y; av.z += vv.z; av.w += vv.w;
                }
                ak.x *= 0.2f; ak.y *= 0.2f; ak.z *= 0.2f; ak.w *= 0.2f;
                av.x *= 0.2f; av.y *= 0.2f; av.z *= 0.2f; av.w *= 0.2f;
                if (type == 1) *(float4*)&g_PV[(lo + r)*DK + c4] = av;
            }
            *(float4*)&ks[r*260 + c4] = ak;
            *(float4*)&vs[r*260 + c4] = av;
        }
    }
    __syncthreads();

    if (type == 2) {
        #pragma unroll
        for (int rr = 0; rr < 4; rr++) {
            int r = wid*4 + rr;
            float s = 0.f;
            #pragma unroll
            for (int m = 0; m < 8; m++) s += vs[r*260 + lane + 32*m];
            #pragma unroll
            for (int o = 16; o; o >>= 1) s += __shfl_xor_sync(0xffffffffu, s, o);
            if (lane == 0) Pm[r] = s * (1.f/256.f);
        }
    }

    {
        float* gout = isPara ? g_PK : g_Kn;
        const bool wr = (type != 2);
        #pragma unroll
        for (int rr = 0; rr < 4; rr++) {
            int r = wid*4 + rr;
            float v[8]; float s = 0.f;
            #pragma unroll
            for (int m = 0; m < 8; m++) { v[m] = ks[r*260 + lane + 32*m]; s += v[m]*v[m]; }
            #pragma unroll
            for (int o = 16; o; o >>= 1) s += __shfl_xor_sync(0xffffffffu, s, o);
            float rinv = 1.f / fmaxf(sqrtf(s), EPSN);
            #pragma unroll
            for (int m = 0; m < 8; m++) {
                float nv = v[m] * rinv;
                ks[r*260 + lane + 32*m] = nv;
                if (wr && r < len) gout[(lo + r)*DK + lane + 32*m] = nv;
            }
        }
    }
    __syncthreads();

    {
        float acc[4] = {0.f, 0.f, 0.f, 0.f};
        #pragma unroll 8
        for (int i4 = 0; i4 < 64; i4++) {
            float4 own = *(const float4*)&ks[lane*260 + i4*4];
            #pragma unroll
            for (int s = 0; s < 4; s++) {
                float4 b = *(const float4*)&ks[(wid + 8*s)*260 + i4*4];
                acc[s] += own.x*b.x + own.y*b.y + own.z*b.z + own.w*b.w;
            }
        }
        #pragma unroll
        for (int s = 0; s < 4; s++) Gs[(wid + 8*s)*33 + lane] = acc[s];
    }
    __syncthreads();

    #pragma unroll
    for (int cc = 0; cc < 4; cc++) {
        int k = wid*4 + cc;
        float v = (lane == k) ? 1.f : 0.f;
        for (int i = 0; i < len; i++) {
            float vi = __shfl_sync(0xffffffffu, v, i);
            if (lane > i && lane < len) {
                float g = bwd ? Gs[(len-1-lane)*33 + (len-1-i)]
                              : Gs[lane*33 + i];
                v -= ALPHA * g * vi;
            }
        }
        Ts[lane*36 + k] = v;
    }
    __syncthreads();

    if (type == 2 && wid == 0) {
        float f = 0.f;
        if (lane < len) {
            float dp = 1.f;
            for (int i = 0; i <= lane; i++) dp *= (1.f / P_DECAY);
            f = BETA * dp * Pm[lane];
        }
        fs[lane] = f;
        __syncwarp();
        float lf = 0.f;
        if (lane < len)
            for (int i = 0; i < lane; i++) lf += Gs[lane*33 + i] * fs[i];
        lfs[lane] = lf;
        __syncwarp();
        float e = 0.f;
        #pragma unroll 8
        for (int k2 = 0; k2 < CH; k2++) e += Ts[lane*36 + k2] * lfs[k2];
        g_c[chunk*CH + lane] = -ALPHA * e + f;
    }

    float ksv[CH];
    #pragma unroll
    for (int m = 0; m < CH; m++) {
        int rl = bwd ? (len - 1 - m) : m;
        ksv[m] = (m < len) ? ks[rl*260 + tid] : 0.f;
    }
    float* Wout = g_W + (size_t)cid * CH * DK;
    #pragma unroll
    for (int j = 0; j < CH; j++) {
        float acc2 = 0.f;
        #pragma unroll
        for (int m4 = 0; m4 < 8; m4++) {
            float4 t = *(const float4*)&Ts[j*36 + m4*4];
            acc2 += t.x*ksv[m4*4] + t.y*ksv[m4*4+1] + t.z*ksv[m4*4+2] + t.w*ksv[m4*4+3];
        }
        Wout[j*DK + tid] = acc2;
    }
}

// ---------------- kernel 3: chunked probe scans (4 concurrent blocks) ----------------
__global__ void __launch_bounds__(256) k_scan(const float* __restrict__ q,
                                              int T, int P, int nchS, int nchP)
{
    __shared__ float a_s[DK];
    __shared__ float sigk_s[CH], sigv_s[CH];
    __shared__ float dpow[CH+1];
    __shared__ float red[8];
    __shared__ float s_inv;

    const int bid = blockIdx.x, tid = threadIdx.x;
    const int wid = tid >> 5, lane = tid & 31;
    const bool fwd  = (bid == 3);
    const bool sent = (bid == 0);
    const float decay = sent ? S_DECAY : P_DECAY;
    const int nch   = sent ? nchS : nchP;
    const int steps = sent ? T : P;
    const float* Kd = sent ? g_Kn : g_PK;
    const float* Vd = sent ? g_V  : g_PV;
    const int slot0 = sent ? 0 : (fwd ? (nchS + nchP) : nchS);

    if (tid == 0) {
        dpow[0] = 1.f;
        for (int i = 0; i < CH; i++) dpow[i+1] = dpow[i] * decay;
    }

    float a;
    if (bid <= 1) {
        float qv = q[tid];
        float x = qv * qv;
        #pragma unroll
        for (int o = 16; o; o >>= 1) x += __shfl_xor_sync(0xffffffffu, x, o);
        if (lane == 0) red[wid] = x;
        __syncthreads();
        if (tid == 0) {
            float s = 0.f;
            #pragma unroll
            for (int w = 0; w < 8; w++) s += red[w];
            s_inv = 1.f / fmaxf(sqrtf(s), EPSN);
        }
        __syncthreads();
        a = qv * s_inv;
    } else {
        a = (bid == 2) ? (1.f/256.f) : 0.f;
    }
    a_s[tid] = a;

    const int j0 = wid * 4;
    float wreg[4][8];
    float creg[4] = {0.f, 0.f, 0.f, 0.f};

    {
        int chunk = fwd ? 0 : (nch - 1);
        const float* Wp = g_W + (size_t)(slot0 + chunk) * CH * DK;
        #pragma unroll
        for (int r = 0; r < 4; r++)
            #pragma unroll
            for (int m = 0; m < 8; m++)
                wreg[r][m] = Wp[(j0 + r)*DK + lane + 32*m];
        if (fwd) {
            #pragma unroll
            for (int r = 0; r < 4; r++) creg[r] = g_c[chunk*CH + j0 + r];
        }
    }

    float outreg = 0.f;

    for (int c = 0; c < nch; c++) {
        const int chunk = fwd ? c : (nch - 1 - c);
        const int lo  = chunk * CH;
        const int len = min(CH, steps - lo);
        const int hi  = lo + len - 1;
        __syncthreads();

        float kreg[CH], vreg[CH];
        #pragma unroll
        for (int j = 0; j < CH; j++) {
            int row = fwd ? (lo + j) : (hi - j);
            row = max(0, min(row, steps - 1));
            kreg[j] = Kd[row*DK + tid];
            vreg[j] = fwd ? 0.f : Vd[row*DK + tid];
        }

        float av[8];
        #pragma unroll
        for (int m = 0; m < 8; m++) av[m] = a_s[lane + 32*m];
        float s[4];
        #pragma unroll
        for (int r = 0; r < 4; r++) {
            float t = 0.f;
            #pragma unroll
            for (int m = 0; m < 8; m++) t += wreg[r][m] * av[m];
            s[r] = t;
        }
        #pragma unroll
        for (int o = 16; o; o >>= 1)
            #pragma unroll
            for (int r = 0; r < 4; r++)
                s[r] += __shfl_xor_sync(0xffffffffu, s[r], o);
        if (lane == 0) {
            #pragma unroll
            for (int r = 0; r < 4; r++) {
                int j = j0 + r;
                float sk = 0.f, sv = 0.f;
                if (j < len) {
                    if (fwd) { sk = -ALPHA * s[r] + creg[r]; }
                    else     { sk = -ALPHA * s[r]; sv = BETA * dpow[j] * s[r]; }
                }
                sigk_s[j] = sk;
                sigv_s[j] = sv;
            }
        }

        if (c + 1 < nch) {
            int nchunk = fwd ? (c + 1) : (nch - 2 - c);
            const float* Wp = g_W + (size_t)(slot0 + nchunk) * CH * DK;
            #pragma unroll
            for (int r = 0; r < 4; r++)
                #pragma unroll
                for (int m = 0; m < 8; m++)
                    wreg[r][m] = Wp[(j0 + r)*DK + lane + 32*m];
            if (fwd) {
                #pragma unroll
                for (int r = 0; r < 4; r++) creg[r] = g_c[nchunk*CH + j0 + r];
            }
        }
        __syncthreads();

        float wsum = 0.f, osum = 0.f;
        #pragma unroll
        for (int j = 0; j < CH; j++) {
            wsum += sigk_s[j] * kreg[j];
            osum += sigv_s[j] * vreg[j];
        }
        outreg += osum;
        a = dpow[len] * (a + wsum);
        a_s[tid] = a;
    }

    if (bid < 3) g_res[bid*DK + tid] = outreg;
    else         g_res[3*DK + tid]   = a;
}

// ---------------- kernel 4: combine ----------------
__device__ __forceinline__ float bred256(float x, float* red)
{
    const int tid = threadIdx.x;
    #pragma unroll
    for (int o = 16; o; o >>= 1) x += __shfl_xor_sync(0xffffffffu, x, o);
    __syncthreads();
    if ((tid & 31) == 0) red[tid >> 5] = x;
    __syncthreads();
    float s = 0.f;
    #pragma unroll
    for (int w = 0; w < 8; w++) s += red[w];
    return s;
}

__global__ void k_final(const float* __restrict__ q, float* __restrict__ out)
{
    __shared__ float red[8];
    const int tid = threadIdx.x;
    float qv  = q[tid];
    float dkv = g_res[3*256 + tid];
    float ssq = bred256(qv*qv, red);
    float ssd = bred256(dkv*dkv, red);
    float dot = bred256(qv*dkv, red);
    float coef = dot / (fmaxf(sqrtf(ssq), EPSN) * fmaxf(sqrtf(ssd), EPSN));
    out[tid] = 0.2f*g_res[tid] + 0.3f*g_res[256 + tid]
             + 0.5f * (BETA * coef) * g_res[512 + tid];
}

// ---------------- launcher ----------------
extern "C" void kernel_launch(void* const* d_in, const int* in_sizes, int n_in,
                              void* d_out, int out_size)
{
    const float* emb = (const float*)d_in[0];
    const float* q   = (const float*)d_in[1];
    const float* Wk  = (const float*)d_in[2];
    const float* bk  = (const float*)d_in[3];
    const float* Wv  = (const float*)d_in[4];
    const float* bv  = (const float*)d_in[5];
    // d_in[6..8] = zero initial memories (collapsed analytically)

    int T = in_sizes[0] / DEMB;     // 1000
    int P = T / 5;                  // 200
    int nchS = (T + CH - 1) / CH;   // 32
    int nchP = (P + CH - 1) / CH;   // 7

    cudaFuncSetAttribute(k_kv, cudaFuncAttributeMaxDynamicSharedMemorySize, KV_DYN_BYTES);
    cudaFuncSetAttribute(k_prep, cudaFuncAttributeMaxDynamicSharedMemorySize, 16640*4);

    k_kv  <<<(T + 7)/8, 256, KV_DYN_BYTES>>>(emb, Wk, bk, Wv, bv, T);
    k_prep<<<nchS + 2*nchP, 256, 16640*4>>>(T, P, nchS, nchP);
    k_scan<<<4, 256>>>(q, T, P, nchS, nchP);
    k_final<<<1, 256>>>(q, (float*)d_out);
}